// round 1
// baseline (speedup 1.0000x reference)
#include <cuda_runtime.h>
#include <cuda_bf16.h>

// Problem constants (reference: N_EDGES=8192, TOTAL_TOKENS=2097152, OUT_CH=128)
#define MAX_EDGES 8192
#define OUT_CH    128

// Scratch: per-edge histogram of the 4 token values. 8192*4 ints = 128 KB.
__device__ int g_hist[MAX_EDGES * 4];

__global__ void zero_hist_kernel(int n) {
    int i = blockIdx.x * blockDim.x + threadIdx.x;
    if (i < n) g_hist[i] = 0;
}

// Each thread owns a contiguous strip of 32 tokens (8 x int4 from each array).
// segment_ids are globally sorted, so a thread sees a non-decreasing run of
// segment ids; accumulate 4 token-counts packed in 16-bit fields of a u64 and
// flush via atomicAdd only on segment transitions (~1.1 segments per strip).
__global__ void hist_kernel(const int4* __restrict__ tokens4,
                            const int4* __restrict__ segs4,
                            int n4) {
    const int V = 8;  // int4 groups per thread -> 32 tokens
    long long base = (long long)(blockIdx.x * blockDim.x + threadIdx.x) * V;

    int cur = -1;
    unsigned long long cnt = 0ull;

#define FLUSH_CNT()                                                         \
    do {                                                                    \
        int c0 = (int)(cnt & 0xFFFFull);                                    \
        int c1 = (int)((cnt >> 16) & 0xFFFFull);                            \
        int c2 = (int)((cnt >> 32) & 0xFFFFull);                            \
        int c3 = (int)(cnt >> 48);                                          \
        int b  = cur * 4;                                                   \
        if (c0) atomicAdd(&g_hist[b + 0], c0);                              \
        if (c1) atomicAdd(&g_hist[b + 1], c1);                              \
        if (c2) atomicAdd(&g_hist[b + 2], c2);                              \
        if (c3) atomicAdd(&g_hist[b + 3], c3);                              \
    } while (0)

#pragma unroll
    for (int i = 0; i < V; i++) {
        long long idx = base + i;
        if (idx >= n4) break;
        int4 tk = tokens4[idx];
        int4 sg = segs4[idx];

        int ss[4] = {sg.x, sg.y, sg.z, sg.w};
        int tt[4] = {tk.x, tk.y, tk.z, tk.w};
#pragma unroll
        for (int j = 0; j < 4; j++) {
            int s = ss[j];
            if (s != cur) {
                if (cur >= 0) FLUSH_CNT();
                cur = s;
                cnt = 0ull;
            }
            cnt += 1ull << (tt[j] * 16);
        }
    }
    if (cur >= 0) FLUSH_CNT();
#undef FLUSH_CNT
}

// out[e][d] = (sum_t hist[e][t] * E[t][d]) / max(count[e], 1)
// One thread per output element; embedding (2 KB) is L1-resident, hist reads
// broadcast across the 128 threads of an edge.
__global__ void out_kernel(const float* __restrict__ emb,  // [4][128]
                           float* __restrict__ out,        // [E][128]
                           int n_out) {
    int gid = blockIdx.x * blockDim.x + threadIdx.x;
    if (gid >= n_out) return;
    int e = gid >> 7;
    int d = gid & 127;

    int h0 = g_hist[e * 4 + 0];
    int h1 = g_hist[e * 4 + 1];
    int h2 = g_hist[e * 4 + 2];
    int h3 = g_hist[e * 4 + 3];

    float tot = (float)(h0 + h1 + h2 + h3);
    float inv = 1.0f / fmaxf(tot, 1.0f);

    float v = (float)h0 * emb[0 * OUT_CH + d]
            + (float)h1 * emb[1 * OUT_CH + d]
            + (float)h2 * emb[2 * OUT_CH + d]
            + (float)h3 * emb[3 * OUT_CH + d];

    out[gid] = v * inv;
}

extern "C" void kernel_launch(void* const* d_in, const int* in_sizes, int n_in,
                              void* d_out, int out_size) {
    // Input order (metadata): overlap_similarity f32[E], overlap_length f32[E],
    // tokens i32[T], segment_ids i32[T], embedding f32[4*128], n_edges i32[1]
    const int*   tokens  = (const int*)d_in[2];
    const int*   segids  = (const int*)d_in[3];
    const float* emb     = (const float*)d_in[4];
    float*       out     = (float*)d_out;

    int total_tokens = in_sizes[2];
    int n_edges      = out_size / OUT_CH;

    // 1) zero the histogram scratch
    {
        int n = n_edges * 4;
        int threads = 256;
        int blocks = (n + threads - 1) / threads;
        zero_hist_kernel<<<blocks, threads>>>(n);
    }

    // 2) histogram (tokens count is a multiple of 4 here: 2097152)
    {
        int n4 = total_tokens / 4;            // int4 groups
        int threads_needed = (n4 + 7) / 8;    // 8 int4 groups per thread
        int threads = 256;
        int blocks = (threads_needed + threads - 1) / threads;
        hist_kernel<<<blocks, threads>>>((const int4*)tokens, (const int4*)segids, n4);
    }

    // 3) tiny epilogue: hist x embedding -> output
    {
        int threads = 256;
        int blocks = (out_size + threads - 1) / threads;
        out_kernel<<<blocks, threads>>>(emb, out, out_size);
    }
}

// round 2
// speedup vs baseline: 1.1335x; 1.1335x over previous
#include <cuda_runtime.h>
#include <cuda_bf16.h>

#define OUT_CH 128

// One warp per edge. segment_ids are globally sorted, so edge e's tokens are
// the contiguous range [lower_bound(segs, e), lower_bound(segs, e+1)).
// Single kernel: no scratch, no zero pass, no atomics.
__global__ void __launch_bounds__(256)
edge_mean_kernel(const int* __restrict__ tokens,
                 const int* __restrict__ segs,
                 const float* __restrict__ emb,   // [4][128]
                 float* __restrict__ out,         // [E][128]
                 int total_tokens,
                 int n_edges) {
    const int warp_id = (blockIdx.x * blockDim.x + threadIdx.x) >> 5;
    const int lane    = threadIdx.x & 31;
    if (warp_id >= n_edges) return;
    const int e = warp_id;

    // lower_bound(segs, total_tokens, e): first index with segs[i] >= e.
    // All lanes run the same search -> broadcast loads, no divergence.
    int lo = 0, hi = total_tokens;
    while (lo < hi) {
        int mid = (lo + hi) >> 1;
        if (__ldg(&segs[mid]) < e) lo = mid + 1; else hi = mid;
    }
    const int start = lo;

    // lower_bound for e+1 (search only the suffix [start, total_tokens)).
    lo = start; hi = total_tokens;
    while (lo < hi) {
        int mid = (lo + hi) >> 1;
        if (__ldg(&segs[mid]) < e + 1) lo = mid + 1; else hi = mid;
    }
    const int end = lo;

    // Count the 4 token values over [start, end), 32 lanes strided.
    int c0 = 0, c1 = 0, c2 = 0, c3 = 0;
    for (int i = start + lane; i < end; i += 32) {
        int t = __ldg(&tokens[i]);
        c0 += (t == 0);
        c1 += (t == 1);
        c2 += (t == 2);
        c3 += (t == 3);
    }
    c0 = __reduce_add_sync(0xFFFFFFFFu, (unsigned)c0);
    c1 = __reduce_add_sync(0xFFFFFFFFu, (unsigned)c1);
    c2 = __reduce_add_sync(0xFFFFFFFFu, (unsigned)c2);
    c3 = __reduce_add_sync(0xFFFFFFFFu, (unsigned)c3);

    const float f0 = (float)c0, f1 = (float)c1, f2 = (float)c2, f3 = (float)c3;
    const float inv = 1.0f / fmaxf(f0 + f1 + f2 + f3, 1.0f);

    // Each lane produces 4 consecutive channels -> one float4 store per lane,
    // a fully coalesced 512-byte row per warp. Embedding rows via float4.
    const int d = lane * 4;
    const float4 e0 = *(const float4*)(emb + 0 * OUT_CH + d);
    const float4 e1 = *(const float4*)(emb + 1 * OUT_CH + d);
    const float4 e2 = *(const float4*)(emb + 2 * OUT_CH + d);
    const float4 e3 = *(const float4*)(emb + 3 * OUT_CH + d);

    float4 r;
    r.x = (f0 * e0.x + f1 * e1.x + f2 * e2.x + f3 * e3.x) * inv;
    r.y = (f0 * e0.y + f1 * e1.y + f2 * e2.y + f3 * e3.y) * inv;
    r.z = (f0 * e0.z + f1 * e1.z + f2 * e2.z + f3 * e3.z) * inv;
    r.w = (f0 * e0.w + f1 * e1.w + f2 * e2.w + f3 * e3.w) * inv;

    *(float4*)(out + (long long)e * OUT_CH + d) = r;
}

extern "C" void kernel_launch(void* const* d_in, const int* in_sizes, int n_in,
                              void* d_out, int out_size) {
    // Inputs: 0 overlap_similarity f32[E], 1 overlap_length f32[E],
    //         2 tokens i32[T], 3 segment_ids i32[T], 4 embedding f32[4*128],
    //         5 n_edges
    const int*   tokens = (const int*)d_in[2];
    const int*   segs   = (const int*)d_in[3];
    const float* emb    = (const float*)d_in[4];
    float*       out    = (float*)d_out;

    const int total_tokens = in_sizes[2];
    const int n_edges      = out_size / OUT_CH;

    const int threads = 256;                    // 8 warps -> 8 edges per block
    const int blocks  = (n_edges * 32 + threads - 1) / threads;
    edge_mean_kernel<<<blocks, threads>>>(tokens, segs, emb, out,
                                          total_tokens, n_edges);
}